// round 17
// baseline (speedup 1.0000x reference)
#include <cuda_runtime.h>
#include <cuda_fp16.h>
#include <cstdint>

#define NT 128
#define BM 128
#define BN 32
#define DH 128
#define HCONST 16
#define NKV 64            // S/BN for S=2048

// ---- gmem tile-image layout (per 32-row tile) ----
#define KH_O 0                   // K fp16: 32 x 256B (swizzled)      8192 B
#define VTH_O 8192               // V^T fp16: 128 d-rows x 80B        10240 B
#define IMGSZ 18432
#define KSZ 8192
#define VSZ 10240

// ---- SMEM byte layout (main kernel) ----
#define QH_OFF 0                 // Q fp16: 128 rows x 256B (swizzled) 32768 B
#define KBUF0  32768             // K double buffer: 2 x 8192
#define VBUF0  49152             // V triple buffer: 3 x 10240
#define SMEM_TOTAL 79872         // -> 2 CTAs/SM (159.7 KB)

// 1/sqrt(128) * log2(e)
#define SCALE2 0.1275200917303861f

// Precomputed KV tile images: [B][H][NKV] x IMGSZ bytes
__device__ __align__(128) char g_kv[2 * HCONST * NKV * (size_t)IMGSZ];

__device__ __forceinline__ uint32_t smem_u32(const void* p) {
    uint32_t a;
    asm("{ .reg .u64 t; cvta.to.shared.u64 t, %1; cvt.u32.u64 %0, t; }" : "=r"(a) : "l"(p));
    return a;
}
__device__ __forceinline__ void ldsm4(uint32_t r[4], uint32_t addr) {
    asm volatile("ldmatrix.sync.aligned.m8n8.x4.shared.b16 {%0,%1,%2,%3}, [%4];"
                 : "=r"(r[0]), "=r"(r[1]), "=r"(r[2]), "=r"(r[3]) : "r"(addr));
}
__device__ __forceinline__ void mma16816(float c[4], const uint32_t a[4], const uint32_t b[2]) {
    asm volatile("mma.sync.aligned.m16n8k16.row.col.f32.f16.f16.f32 "
                 "{%0,%1,%2,%3}, {%4,%5,%6,%7}, {%8,%9}, {%0,%1,%2,%3};"
                 : "+f"(c[0]), "+f"(c[1]), "+f"(c[2]), "+f"(c[3])
                 : "r"(a[0]), "r"(a[1]), "r"(a[2]), "r"(a[3]), "r"(b[0]), "r"(b[1]));
}
// zero-accumulate: d = a*b + 0
__device__ __forceinline__ void mma16816_z(float d[4], const uint32_t a[4], const uint32_t b[2]) {
    asm volatile("mma.sync.aligned.m16n8k16.row.col.f32.f16.f16.f32 "
                 "{%0,%1,%2,%3}, {%4,%5,%6,%7}, {%8,%9}, {%10,%11,%12,%13};"
                 : "=f"(d[0]), "=f"(d[1]), "=f"(d[2]), "=f"(d[3])
                 : "r"(a[0]), "r"(a[1]), "r"(a[2]), "r"(a[3]), "r"(b[0]), "r"(b[1]),
                   "f"(0.0f), "f"(0.0f), "f"(0.0f), "f"(0.0f));
}
__device__ __forceinline__ float ex2f(float x) {
    float y; asm("ex2.approx.f32 %0, %1;" : "=f"(y) : "f"(x)); return y;
}
__device__ __forceinline__ void cp16(uint32_t saddr, const char* g) {
    asm volatile("cp.async.cg.shared.global [%0], [%1], 16;" :: "r"(saddr), "l"(g));
}
#define CP_COMMIT() asm volatile("cp.async.commit_group;" ::: "memory")
#define CP_WAIT0()  asm volatile("cp.async.wait_group 0;" ::: "memory")
#define CP_WAIT1()  asm volatile("cp.async.wait_group 1;" ::: "memory")

// Copy BYTES (multiple of NT*16 = 2048) from gmem image to smem.
template <int BYTES>
__device__ __forceinline__ void copy_img(uint32_t sdst, const char* g, int tid) {
    #pragma unroll
    for (int o = 0; o < BYTES; o += NT * 16)
        cp16(sdst + o + tid * 16, g + o + tid * 16);
}

__device__ __forceinline__ uint32_t pack_h2(float x, float y) {
    __half2 v = __floats2half2_rn(x, y);
    return *(uint32_t*)&v;
}

// ================= prepass: K,V fp32 -> fp16 tile images (direct stores) =================
#define PNT 256
__global__ void __launch_bounds__(PNT, 4)
kv_prepass(const float* __restrict__ K, const float* __restrict__ V, int S, int H)
{
    const int t = blockIdx.x, h = blockIdx.y, b = blockIdx.z;
    const int tid = threadIdx.x;
    const int rs = H * DH;
    char* img = g_kv + ((size_t)((b * HCONST + h) * NKV + t)) * IMGSZ;
    const float* kg = K + ((size_t)(b * S + t * BN)) * rs + (size_t)h * DH;
    const float* vg = V + ((size_t)(b * S + t * BN)) * rs + (size_t)h * DH;
    // K: 32 rows x 128 cols fp32 -> swizzled fp16 (1024 float4 items)
    #pragma unroll
    for (int it = 0; it < 4; it++) {
        int idx = tid + PNT * it;                // 0..1023
        int r = idx >> 5, c4 = idx & 31;
        float4 v = *(const float4*)(kg + (size_t)r * rs + c4 * 4);
        uint32_t w0 = pack_h2(v.x, v.y);
        uint32_t w1 = pack_h2(v.z, v.w);
        uint32_t o = (uint32_t)r * 256 + ((((uint32_t)(c4 >> 1)) ^ (r & 7)) << 4) + (c4 & 1) * 8;
        *(uint2*)(img + KH_O + o) = make_uint2(w0, w1);
    }
    // V^T: 128 d-rows x 32 n (80B rows); 512 items (a=n-pair 0..15, dc=d-chunk 0..31)
    #pragma unroll
    for (int it = 0; it < 2; it++) {
        int idx = tid + PNT * it;                // 0..511
        int a = idx & 15, dc = idx >> 4;
        float4 v0 = *(const float4*)(vg + (size_t)(2 * a) * rs + dc * 4);
        float4 v1 = *(const float4*)(vg + (size_t)(2 * a + 1) * rs + dc * 4);
        const float* e0 = (const float*)&v0;
        const float* e1 = (const float*)&v1;
        #pragma unroll
        for (int i = 0; i < 4; i++) {
            uint32_t w = pack_h2(e0[i], e1[i]);
            uint32_t o = (uint32_t)(dc * 4 + i) * 80 + a * 4;
            *(uint32_t*)(img + VTH_O + o) = w;
        }
    }
}

// ---- MMA sub-blocks (M=32 per warp, BN=32) ----
// QK ks-block: 2 Q ldsm + 2 K ldsm + 8 MMAs. Z=true -> zero-accumulate.
template <bool Z>
__device__ __forceinline__ void qk_ks(float sacc[2][4][4], uint32_t qoffH, uint32_t kb_,
                                      int ks, uint32_t swz, uint32_t hiA, uint32_t kh8)
{
    uint32_t qh0[4], qh1[4];
    const uint32_t qsw = (((((uint32_t)ks << 1) | hiA) ^ swz) << 4);
    ldsm4(qh0, qoffH + qsw);
    ldsm4(qh1, qoffH + 4096 + qsw);          // m1: +16 rows * 256B
    const uint32_t kch = (((((uint32_t)ks << 1) | kh8) ^ swz) << 4);
    #pragma unroll
    for (int t = 0; t < 2; t++) {
        uint32_t kh[4];
        ldsm4(kh, kb_ + (uint32_t)t * 4096 + kch);
        if (Z) {
            mma16816_z(sacc[0][2*t], qh0, kh);  mma16816_z(sacc[0][2*t+1], qh0, kh+2);
            mma16816_z(sacc[1][2*t], qh1, kh);  mma16816_z(sacc[1][2*t+1], qh1, kh+2);
        } else {
            mma16816(sacc[0][2*t],   qh0, kh);  mma16816(sacc[0][2*t+1],   qh0, kh+2);
            mma16816(sacc[1][2*t],   qh1, kh);  mma16816(sacc[1][2*t+1],   qh1, kh+2);
        }
    }
}
// PV s-block: 8 V ldsm + 32 MMAs (s in {0,1}: 16-n k-slice; both m reuse vh)
__device__ __forceinline__ void pv_s(float oacc[2][16][4], const uint32_t pF[2][8],
                                     uint32_t vb_, int s)
{
    #pragma unroll
    for (int u = 0; u < 8; u++) {
        uint32_t vh[4];
        ldsm4(vh, vb_ + (uint32_t)u * 1280 + (uint32_t)s * 32);
        mma16816(oacc[0][2*u],   pF[0] + 4*s, vh);   mma16816(oacc[0][2*u+1], pF[0] + 4*s, vh+2);
        mma16816(oacc[1][2*u],   pF[1] + 4*s, vh);   mma16816(oacc[1][2*u+1], pF[1] + 4*s, vh+2);
    }
}

// ---- softmax one m-half (4 frags) -> pFm[8], l accumulation ----
__device__ __forceinline__ void softmax_m(const float sacc[4][4], uint32_t* pFm,
                                          float& la, float& lb, int n0, int r0m,
                                          bool causal, int lane)
{
    const bool needmask = causal && (n0 + BN - 1 > r0m);
    #pragma unroll
    for (int nt = 0; nt < 4; nt++) {
        float p0 = ex2f(sacc[nt][0]);
        float p1 = ex2f(sacc[nt][1]);
        float p2 = ex2f(sacc[nt][2]);
        float p3 = ex2f(sacc[nt][3]);
        if (needmask) {
            int c0 = n0 + 8 * nt + 2 * (lane & 3);
            if (c0 > r0m) p0 = 0.0f;
            if (c0 + 1 > r0m) p1 = 0.0f;
            if (c0 > r0m + 8) p2 = 0.0f;
            if (c0 + 1 > r0m + 8) p3 = 0.0f;
        }
        la += p0 + p1;
        lb += p2 + p3;
        pFm[2*nt]   = pack_h2(p0, p1);
        pFm[2*nt+1] = pack_h2(p2, p3);
    }
}

__global__ void __launch_bounds__(NT, 2)
fa_hmma14(const float* __restrict__ Q, const int* __restrict__ causal_flag,
          float* __restrict__ O, int S, int H)
{
    extern __shared__ char smem[];
    const uint32_t sb = smem_u32(smem);
    const int tid  = threadIdx.x;
    const int lane = tid & 31;
    const int wid  = tid >> 5;                      // 0..3, each owns 32 q-rows
    const int qi = gridDim.x - 1 - blockIdx.x;      // longest CTAs first
    const int h = blockIdx.y, b = blockIdx.z;
    const int q0 = qi * BM;
    const int rs = H * DH;
    const bool causal = (causal_flag[0] != 0);
    const int ntiles = causal ? 4 * (qi + 1) : (S / BN);

    const uint32_t swz = lane & 7;
    const uint32_t hiA = (uint32_t)lane >> 4;
    const uint32_t kh8 = ((uint32_t)lane >> 3) & 1;
    const uint32_t bnl = 8 * hiA + swz;
    const uint32_t qoffH = sb + QH_OFF + ((uint32_t)wid * 32 + (lane & 15)) * 256;
    const int r0 = q0 + wid * 32 + (lane >> 2);     // m0: r0, r0+8; m1: r0+16, r0+24

    const char* kvbase = g_kv + ((size_t)((b * HCONST + h) * NKV)) * IMGSZ;

    // ---- issue K0,V0 + K1,V1 copies (ntiles >= 4 always) ----
    copy_img<KSZ>(sb + KBUF0, kvbase + KH_O, tid);
    copy_img<VSZ>(sb + VBUF0, kvbase + VTH_O, tid);
    CP_COMMIT();
    copy_img<KSZ>(sb + KBUF0 + KSZ, kvbase + IMGSZ + KH_O, tid);
    copy_img<VSZ>(sb + VBUF0 + VSZ, kvbase + IMGSZ + VTH_O, tid);
    CP_COMMIT();

    // ---- convert Q tile to fp16 (scale*log2e folded), overlaps copies ----
    {
        const float* qg = Q + ((size_t)(b * S + q0)) * rs + (size_t)h * DH;
        #pragma unroll
        for (int it = 0; it < 32; it++) {
            int idx = tid + NT * it;                 // 0..4095
            int r = idx >> 5, c4 = idx & 31;
            float4 v = *(const float4*)(qg + (size_t)r * rs + c4 * 4);
            uint32_t w0 = pack_h2(v.x * SCALE2, v.y * SCALE2);
            uint32_t w1 = pack_h2(v.z * SCALE2, v.w * SCALE2);
            uint32_t o = (uint32_t)r * 256 + ((((uint32_t)(c4 >> 1)) ^ (r & 7)) << 4) + (c4 & 1) * 8;
            *(uint2*)(smem + QH_OFF + o) = make_uint2(w0, w1);
        }
    }
    CP_WAIT0();
    __syncthreads();

    float oacc[2][16][4];
    #pragma unroll
    for (int m = 0; m < 2; m++)
        #pragma unroll
        for (int t = 0; t < 16; t++)
            #pragma unroll
            for (int e = 0; e < 4; e++) oacc[m][t][e] = 0.0f;
    float l[4] = {0.0f, 0.0f, 0.0f, 0.0f};
    uint32_t pF[2][8];
    float sacc[2][4][4];

    // ---- prologue: QK(0) ----
    {
        const uint32_t kb_ = sb + KBUF0 + bnl * 256;   // K buf 0
        qk_ks<true>(sacc, qoffH, kb_, 0, swz, hiA, kh8);
        #pragma unroll
        for (int ks = 1; ks < 8; ks++)
            qk_ks<false>(sacc, qoffH, kb_, ks, swz, hiA, kh8);
    }
    __syncthreads();   // all warps done with Kbuf0 before K(2) copy overwrites it

    // ---- main loop: single barrier per tile; K double, V triple buffered ----
    int vm0 = 0, vm1 = 1, vm2 = 2;   // Vbuf indices of tiles j, j+1, j+2
    for (int j = 0; j < ntiles - 1; j++) {
        const uint32_t kb_ = sb + KBUF0 + (uint32_t)((j + 1) & 1) * KSZ + bnl * 256;  // K(j+1)
        const uint32_t vb_ = sb + VBUF0 + (uint32_t)vm0 * VSZ + bnl * 80 + kh8 * 16;  // V(j)
        const bool more2 = (j + 2 < ntiles);
        const char* g2 = kvbase + (size_t)(j + 2) * IMGSZ;
        const int n0 = j * BN;

        if (more2)
            copy_img<KSZ>(sb + KBUF0 + (uint32_t)(j & 1) * KSZ, g2 + KH_O, tid);
        CP_COMMIT();
        if (more2)
            copy_img<VSZ>(sb + VBUF0 + (uint32_t)vm2 * VSZ, g2 + VTH_O, tid);
        CP_COMMIT();

        // softmax(j): consumes sacc, fills pF
        softmax_m(sacc[0], pF[0], l[0], l[1], n0, r0,      causal, lane);
        softmax_m(sacc[1], pF[1], l[2], l[3], n0, r0 + 16, causal, lane);

        qk_ks<true>(sacc, qoffH, kb_, 0, swz, hiA, kh8);   pv_s(oacc, pF, vb_, 0);
        qk_ks<false>(sacc, qoffH, kb_, 1, swz, hiA, kh8);  pv_s(oacc, pF, vb_, 1);
        qk_ks<false>(sacc, qoffH, kb_, 2, swz, hiA, kh8);
        qk_ks<false>(sacc, qoffH, kb_, 3, swz, hiA, kh8);
        qk_ks<false>(sacc, qoffH, kb_, 4, swz, hiA, kh8);
        qk_ks<false>(sacc, qoffH, kb_, 5, swz, hiA, kh8);
        qk_ks<false>(sacc, qoffH, kb_, 6, swz, hiA, kh8);
        qk_ks<false>(sacc, qoffH, kb_, 7, swz, hiA, kh8);

        int tmp = vm0; vm0 = vm1; vm1 = vm2; vm2 = tmp;

        CP_WAIT1();        // K(j+2) group landed (V group may still fly)
        __syncthreads();   // single barrier per tile
    }

    // ---- tail: softmax + PV of tile (ntiles-1) ----
    {
        CP_WAIT0();        // ensure V(ntiles-1) landed
        const uint32_t vb_ = sb + VBUF0 + (uint32_t)vm0 * VSZ + bnl * 80 + kh8 * 16;
        const int n0 = (ntiles - 1) * BN;
        softmax_m(sacc[0], pF[0], l[0], l[1], n0, r0,      causal, lane);
        softmax_m(sacc[1], pF[1], l[2], l[3], n0, r0 + 16, causal, lane);
        pv_s(oacc, pF, vb_, 0);
        pv_s(oacc, pF, vb_, 1);
    }

    // ---- epilogue ----
    #pragma unroll
    for (int i = 0; i < 4; i++) {
        l[i] += __shfl_xor_sync(0xffffffffu, l[i], 1);
        l[i] += __shfl_xor_sync(0xffffffffu, l[i], 2);
    }
    const int cofs = 2 * (lane & 3);
    #pragma unroll
    for (int m = 0; m < 2; m++) {
        const float ia = 1.0f / l[2*m], ib = 1.0f / l[2*m + 1];
        float* oa = O + ((size_t)(b * S + r0 + 16*m)) * rs + (size_t)h * DH;
        float* ob = O + ((size_t)(b * S + r0 + 16*m + 8)) * rs + (size_t)h * DH;
        #pragma unroll
        for (int t = 0; t < 16; t++) {
            *(float2*)(oa + 8 * t + cofs) = make_float2(oacc[m][t][0] * ia, oacc[m][t][1] * ia);
            *(float2*)(ob + 8 * t + cofs) = make_float2(oacc[m][t][2] * ib, oacc[m][t][3] * ib);
        }
    }
}

extern "C" void kernel_launch(void* const* d_in, const int* in_sizes, int n_in,
                              void* d_out, int out_size) {
    const float* q = (const float*)d_in[0];
    const float* k = (const float*)d_in[1];
    const float* v = (const float*)d_in[2];
    const int* causal = (const int*)d_in[3];
    float* out = (float*)d_out;

    const int B = 2, H = 16, D = 128;
    const int S = in_sizes[0] / (B * H * D);   // 2048

    dim3 pgrid(S / BN, H, B);
    kv_prepass<<<pgrid, PNT>>>(k, v, S, H);

    cudaFuncSetAttribute(fa_hmma14, cudaFuncAttributeMaxDynamicSharedMemorySize, SMEM_TOTAL);
    dim3 grid(S / BM, H, B);
    fa_hmma14<<<grid, NT, SMEM_TOTAL>>>(q, causal, out, S, H);
}